// round 17
// baseline (speedup 1.0000x reference)
#include <cuda_runtime.h>
#include <cuda_fp16.h>
#include <cstdint>
#include <cstddef>

// Problem constants (reference: N=50000, E=800000, 128->128->64)
#define MAXN 50048
#define MAXE 800000
#define DIN  128
#define DHID 128
#define DOUT 64

// Scratch (static device globals -- no allocation anywhere).
// Only referenced from device code.
__device__ __half g_ht1 [(size_t)MAXN * DHID];  // fp16: x @ W1 (UNSCALED)
__device__ __half g_agg1[(size_t)MAXN * DHID];  // fp16: relu(layer-1 output + b1)
__device__ __half g_ht2 [(size_t)MAXN * DOUT];  // fp16: (agg1 @ W2) * dinv[row]
__device__ float  g_dinv[MAXN];
__device__ int    g_deg [MAXN];
__device__ int    g_rows[MAXN];                 // CSR segment starts (atomic-allocated)
__device__ int    g_cur [MAXN];                 // fill cursors
__device__ int    g_ctr;                        // global segment allocator
__device__ unsigned short g_csr[MAXE];          // src node per CSR slot (ids < 65536)

// ---------------------------------------------------------------------------
// CSR build (runs on side stream, overlapped with k_gemm<1>)
// ---------------------------------------------------------------------------
__global__ void k_zero(int n) {
    int i = blockIdx.x * blockDim.x + threadIdx.x;
    if (i < n) g_deg[i] = 0;
    if (i == 0) g_ctr = 0;
}

// 8 edges per thread (2x int4 loads) -- deep MLP over atomic latency
__global__ void k_count(const int* __restrict__ dst, int ne) {
    int t = blockIdx.x * blockDim.x + threadIdx.x;
    int e = t * 8;
    if (e + 7 < ne) {
        int4 d0 = *(const int4*)(dst + e);
        int4 d1 = *(const int4*)(dst + e + 4);
        atomicAdd(&g_deg[d0.x], 1);
        atomicAdd(&g_deg[d0.y], 1);
        atomicAdd(&g_deg[d0.z], 1);
        atomicAdd(&g_deg[d0.w], 1);
        atomicAdd(&g_deg[d1.x], 1);
        atomicAdd(&g_deg[d1.y], 1);
        atomicAdd(&g_deg[d1.z], 1);
        atomicAdd(&g_deg[d1.w], 1);
    } else {
        for (; e < ne; e++) atomicAdd(&g_deg[__ldg(dst + e)], 1);
    }
}

// Segment allocation: block-wide exclusive scan of degrees (shfl) + ONE
// atomicAdd on g_ctr per block. Segment order is arbitrary -- each node only
// needs its own contiguous [rows[i], rows[i]+deg[i]) range. Computes dinv too.
__global__ void __launch_bounds__(256) k_alloc(int n) {
    __shared__ int wsum[8];
    __shared__ int sbase;
    int tid = threadIdx.x;
    int lane = tid & 31, wid = tid >> 5;
    int i = blockIdx.x * 256 + tid;
    int v = (i < n) ? g_deg[i] : 0;

    int incl = v;
#pragma unroll
    for (int o = 1; o < 32; o <<= 1) {
        int t = __shfl_up_sync(0xffffffffu, incl, o);
        if (lane >= o) incl += t;
    }
    if (lane == 31) wsum[wid] = incl;
    __syncthreads();
    if (tid < 8) {
        int ws = wsum[tid];
        int incl8 = ws;
#pragma unroll
        for (int o = 1; o < 8; o <<= 1) {
            int t = __shfl_up_sync(0xffu, incl8, o);
            if (tid >= o) incl8 += t;
        }
        wsum[tid] = incl8 - ws;                  // exclusive warp offset
        if (tid == 7) sbase = atomicAdd(&g_ctr, incl8);  // block base
    }
    __syncthreads();
    if (i < n) {
        int r = sbase + wsum[wid] + (incl - v);
        g_rows[i] = r;
        g_cur[i] = r;
        g_dinv[i] = rsqrtf((float)v + 1.0f);
    }
}

// 8 edges per thread: issue all 8 independent atomics first, then the 8
// dependent scatter stores (u16) -- overlaps the ~320cyc atomic-return latency.
__global__ void k_fill(const int* __restrict__ src, const int* __restrict__ dst, int ne) {
    int t = blockIdx.x * blockDim.x + threadIdx.x;
    int e = t * 8;
    if (e + 7 < ne) {
        int4 d0 = *(const int4*)(dst + e);
        int4 d1 = *(const int4*)(dst + e + 4);
        int4 s0 = *(const int4*)(src + e);
        int4 s1 = *(const int4*)(src + e + 4);
        int p0 = atomicAdd(&g_cur[d0.x], 1);
        int p1 = atomicAdd(&g_cur[d0.y], 1);
        int p2 = atomicAdd(&g_cur[d0.z], 1);
        int p3 = atomicAdd(&g_cur[d0.w], 1);
        int p4 = atomicAdd(&g_cur[d1.x], 1);
        int p5 = atomicAdd(&g_cur[d1.y], 1);
        int p6 = atomicAdd(&g_cur[d1.z], 1);
        int p7 = atomicAdd(&g_cur[d1.w], 1);
        g_csr[p0] = (unsigned short)s0.x;
        g_csr[p1] = (unsigned short)s0.y;
        g_csr[p2] = (unsigned short)s0.z;
        g_csr[p3] = (unsigned short)s0.w;
        g_csr[p4] = (unsigned short)s1.x;
        g_csr[p5] = (unsigned short)s1.y;
        g_csr[p6] = (unsigned short)s1.z;
        g_csr[p7] = (unsigned short)s1.w;
    } else {
        for (; e < ne; e++) {
            int d = __ldg(dst + e);
            g_csr[atomicAdd(&g_cur[d], 1)] = (unsigned short)__ldg(src + e);
        }
    }
}

// ---------------------------------------------------------------------------
// tf32 helpers
// ---------------------------------------------------------------------------
__device__ __forceinline__ uint32_t f2tf32(float f) {
    uint32_t r;
    asm("cvt.rna.tf32.f32 %0, %1;" : "=r"(r) : "f"(f));
    return r;
}

__device__ __forceinline__ void mma_tf32(float c[4],
    uint32_t a0, uint32_t a1, uint32_t a2, uint32_t a3,
    uint32_t b0, uint32_t b1)
{
    asm volatile(
        "mma.sync.aligned.m16n8k8.row.col.f32.tf32.tf32.f32 "
        "{%0,%1,%2,%3}, {%4,%5,%6,%7}, {%8,%9}, {%0,%1,%2,%3};"
        : "+f"(c[0]), "+f"(c[1]), "+f"(c[2]), "+f"(c[3])
        : "r"(a0), "r"(a1), "r"(a2), "r"(a3), "r"(b0), "r"(b1));
}

// ---------------------------------------------------------------------------
// Tensor-core GEMM.
//   LAYER==1: ht1 = fp16( x @ W1 )   (UNSCALED -- concurrent with CSR build)
//   LAYER==2: ht2 = fp16( (agg1 @ W2) * dinv[row] )
// ---------------------------------------------------------------------------
template <int LAYER>
__global__ void __launch_bounds__(256, 2) k_gemm(
    const float* __restrict__ A_in, const float* __restrict__ B, int n)
{
    constexpr int NCOL = (LAYER == 1) ? DHID : DOUT;
    constexpr int BM = 128;
    constexpr int WN = NCOL / 4;
    constexpr int MA = 4;
    constexpr int NA = WN / 8;
    constexpr int BSTRIDE = NCOL + 8;

    __half* HT = (LAYER == 1) ? g_ht1 : g_ht2;

    __shared__ uint32_t As[BM][36];
    __shared__ uint32_t Bs[32][BSTRIDE];

    const int tid  = threadIdx.x;
    const int wid  = tid >> 5;
    const int lane = tid & 31;
    const int g    = lane >> 2;
    const int tg   = lane & 3;
    const int warp_m = (wid >> 2) * 64;
    const int warp_n = (wid & 3) * WN;
    const int row0 = blockIdx.x * BM;

    float acc[MA][NA][4];
#pragma unroll
    for (int am = 0; am < MA; am++)
#pragma unroll
        for (int an = 0; an < NA; an++)
#pragma unroll
            for (int i = 0; i < 4; i++) acc[am][an][i] = 0.0f;

#pragma unroll 1
    for (int kc = 0; kc < 4; kc++) {
#pragma unroll
        for (int i = tid; i < BM * 8; i += 256) {
            int r = i >> 3, c4 = i & 7;
            int grow = row0 + r;
            float4 v = make_float4(0.f, 0.f, 0.f, 0.f);
            if (grow < n) {
                if (LAYER == 1) {
                    v = ((const float4*)(A_in + (size_t)grow * 128))[kc * 8 + c4];
                } else {
                    uint2 hv = *(const uint2*)(g_agg1 + (size_t)grow * 128 + kc * 32 + c4 * 4);
                    float2 p0 = __half22float2(*(__half2*)&hv.x);
                    float2 p1 = __half22float2(*(__half2*)&hv.y);
                    v = make_float4(p0.x, p0.y, p1.x, p1.y);
                }
            }
            uint4 t;
            t.x = f2tf32(v.x); t.y = f2tf32(v.y);
            t.z = f2tf32(v.z); t.w = f2tf32(v.w);
            ((uint4*)&As[r][0])[c4] = t;
        }
        constexpr int NV = 32 * NCOL / 4;
#pragma unroll
        for (int i = tid; i < NV; i += 256) {
            int k = i / (NCOL / 4), c = i % (NCOL / 4);
            float4 v = ((const float4*)(B + (size_t)(kc * 32 + k) * NCOL))[c];
            uint4 t;
            t.x = f2tf32(v.x); t.y = f2tf32(v.y);
            t.z = f2tf32(v.z); t.w = f2tf32(v.w);
            ((uint4*)&Bs[k][0])[c] = t;
        }
        __syncthreads();

#pragma unroll
        for (int ks = 0; ks < 4; ks++) {
            const int k0 = ks * 8;
            uint32_t af[MA][4];
#pragma unroll
            for (int am = 0; am < MA; am++) {
                int r = warp_m + am * 16 + g;
                af[am][0] = As[r]    [k0 + tg];
                af[am][1] = As[r + 8][k0 + tg];
                af[am][2] = As[r]    [k0 + tg + 4];
                af[am][3] = As[r + 8][k0 + tg + 4];
            }
            uint32_t bf[NA][2];
#pragma unroll
            for (int an = 0; an < NA; an++) {
                int c = warp_n + an * 8 + g;
                bf[an][0] = Bs[k0 + tg]    [c];
                bf[an][1] = Bs[k0 + tg + 4][c];
            }
#pragma unroll
            for (int am = 0; am < MA; am++)
#pragma unroll
                for (int an = 0; an < NA; an++)
                    mma_tf32(acc[am][an], af[am][0], af[am][1], af[am][2],
                             af[am][3], bf[an][0], bf[an][1]);
        }
        __syncthreads();
    }

#pragma unroll
    for (int am = 0; am < MA; am++) {
        int r_lo = row0 + warp_m + am * 16 + g;
        int r_hi = r_lo + 8;
        float dv_lo = 1.f, dv_hi = 1.f;
        if (LAYER == 2) {
            dv_lo = (r_lo < n) ? g_dinv[r_lo] : 0.f;
            dv_hi = (r_hi < n) ? g_dinv[r_hi] : 0.f;
        }
#pragma unroll
        for (int an = 0; an < NA; an++) {
            int col = warp_n + an * 8 + tg * 2;
            if (r_lo < n) {
                *(__half2*)(HT + (size_t)r_lo * NCOL + col) =
                    __floats2half2_rn(acc[am][an][0] * dv_lo,
                                      acc[am][an][1] * dv_lo);
            }
            if (r_hi < n) {
                *(__half2*)(HT + (size_t)r_hi * NCOL + col) =
                    __floats2half2_rn(acc[am][an][2] * dv_hi,
                                      acc[am][an][3] * dv_hi);
            }
        }
    }
}

// ---------------------------------------------------------------------------
// CSR gather: one warp per node.  re = rs + deg[w].
// LAYER==1 (ht1 unscaled): agg1[d] = fp16(relu( dv*(ht1[d]*dv + sum ht1[s]*dinv[s]) + b1 ))
// LAYER==2 (ht2 scaled):   out [d] =      relu( dv*(ht2[d]    + sum ht2[s])         + b2 )
// ---------------------------------------------------------------------------
template <int LAYER>
__global__ void __launch_bounds__(256) k_gather(
    float* __restrict__ out_param, const float* __restrict__ bias, int n)
{
    constexpr int NCOL = (LAYER == 1) ? DHID : DOUT;
    const __half* HT = (LAYER == 1) ? g_ht1 : g_ht2;

    int w = (blockIdx.x * 256 + threadIdx.x) >> 5;
    int lane = threadIdx.x & 31;
    if (w >= n) return;

    int rs = 0, re = 0;
    float dv = 0.f;
    if (lane == 0) {
        rs = g_rows[w];
        re = rs + g_deg[w];
        dv = g_dinv[w];
    }
    rs = __shfl_sync(0xffffffffu, rs, 0);
    re = __shfl_sync(0xffffffffu, re, 0);
    dv = __shfl_sync(0xffffffffu, dv, 0);

    if (LAYER == 1) {
        uint2 sr = ((const uint2*)(HT + (size_t)w * NCOL))[lane];
        float2 s0 = __half22float2(*(__half2*)&sr.x);
        float2 s1 = __half22float2(*(__half2*)&sr.y);
        float4 a0 = make_float4(s0.x * dv, s0.y * dv, s1.x * dv, s1.y * dv);
        float4 a1 = make_float4(0.f, 0.f, 0.f, 0.f);
        for (int base = rs; base < re; base += 32) {
            int cnt = min(32, re - base);
            int idx = 0; float dvs = 0.f;
            if (lane < cnt) {
                idx = (int)g_csr[base + lane];
                dvs = __ldg(g_dinv + idx);
            }
            int k = 0;
            for (; k + 2 <= cnt; k += 2) {
                int n0 = __shfl_sync(0xffffffffu, idx, k);
                int n1 = __shfl_sync(0xffffffffu, idx, k + 1);
                float f0 = __shfl_sync(0xffffffffu, dvs, k);
                float f1 = __shfl_sync(0xffffffffu, dvs, k + 1);
                uint2 r0 = ((const uint2*)(HT + (size_t)n0 * NCOL))[lane];
                uint2 r1 = ((const uint2*)(HT + (size_t)n1 * NCOL))[lane];
                float2 p0 = __half22float2(*(__half2*)&r0.x);
                float2 p1 = __half22float2(*(__half2*)&r0.y);
                float2 q0 = __half22float2(*(__half2*)&r1.x);
                float2 q1 = __half22float2(*(__half2*)&r1.y);
                a0.x = fmaf(p0.x, f0, a0.x); a0.y = fmaf(p0.y, f0, a0.y);
                a0.z = fmaf(p1.x, f0, a0.z); a0.w = fmaf(p1.y, f0, a0.w);
                a1.x = fmaf(q0.x, f1, a1.x); a1.y = fmaf(q0.y, f1, a1.y);
                a1.z = fmaf(q1.x, f1, a1.z); a1.w = fmaf(q1.y, f1, a1.w);
            }
            if (k < cnt) {
                int n0 = __shfl_sync(0xffffffffu, idx, k);
                float f0 = __shfl_sync(0xffffffffu, dvs, k);
                uint2 r0 = ((const uint2*)(HT + (size_t)n0 * NCOL))[lane];
                float2 p0 = __half22float2(*(__half2*)&r0.x);
                float2 p1 = __half22float2(*(__half2*)&r0.y);
                a0.x = fmaf(p0.x, f0, a0.x); a0.y = fmaf(p0.y, f0, a0.y);
                a0.z = fmaf(p1.x, f0, a0.z); a0.w = fmaf(p1.y, f0, a0.w);
            }
        }
        float4 bb = ((const float4*)bias)[lane];
        float rx = fmaxf((a0.x + a1.x) * dv + bb.x, 0.f);
        float ry = fmaxf((a0.y + a1.y) * dv + bb.y, 0.f);
        float rz = fmaxf((a0.z + a1.z) * dv + bb.z, 0.f);
        float rw = fmaxf((a0.w + a1.w) * dv + bb.w, 0.f);
        uint2 st;
        *(__half2*)&st.x = __floats2half2_rn(rx, ry);
        *(__half2*)&st.y = __floats2half2_rn(rz, rw);
        ((uint2*)(g_agg1 + (size_t)w * NCOL))[lane] = st;
    } else {
        const __half2* self = (const __half2*)(HT + (size_t)w * NCOL);
        float2 a0 = __half22float2(self[lane]);
        float2 a1 = make_float2(0.f, 0.f);
        for (int base = rs; base < re; base += 32) {
            int cnt = min(32, re - base);
            int idx = (lane < cnt) ? (int)g_csr[base + lane] : 0;
            int k = 0;
            for (; k + 2 <= cnt; k += 2) {
                int n0 = __shfl_sync(0xffffffffu, idx, k);
                int n1 = __shfl_sync(0xffffffffu, idx, k + 1);
                float2 p = __half22float2(((const __half2*)(HT + (size_t)n0 * NCOL))[lane]);
                float2 q = __half22float2(((const __half2*)(HT + (size_t)n1 * NCOL))[lane]);
                a0.x += p.x; a0.y += p.y;
                a1.x += q.x; a1.y += q.y;
            }
            if (k < cnt) {
                int n0 = __shfl_sync(0xffffffffu, idx, k);
                float2 p = __half22float2(((const __half2*)(HT + (size_t)n0 * NCOL))[lane]);
                a0.x += p.x; a0.y += p.y;
            }
        }
        float2 bb = ((const float2*)bias)[lane];
        float2 r = make_float2(fmaxf((a0.x + a1.x) * dv + bb.x, 0.f),
                               fmaxf((a0.y + a1.y) * dv + bb.y, 0.f));
        ((float2*)(out_param + (size_t)w * NCOL))[lane] = r;
    }
}

// ---------------------------------------------------------------------------
extern "C" void kernel_launch(void* const* d_in, const int* in_sizes, int n_in,
                              void* d_out, int out_size)
{
    const float* x  = (const float*)d_in[0];
    const int*   ei = (const int*)  d_in[1];
    const float* W1 = (const float*)d_in[2];
    const float* b1 = (const float*)d_in[3];
    const float* W2 = (const float*)d_in[4];
    const float* b2 = (const float*)d_in[5];
    float* out = (float*)d_out;

    const int n  = in_sizes[0] / DIN;    // 50000
    const int ne = in_sizes[1] / 2;      // 800000
    const int* src = ei;
    const int* dst = ei + ne;

    const int nb_n  = (n + 255) / 256;
    const int nb_e8 = (ne / 8 + 255) / 256;   // 8 edges per thread
    const int nb_g  = (n + 127) / 128;
    const int nb_w  = (n + 7) / 8;

    // Fork: CSR build on side stream, gemm1 (graph-independent) on main.
    cudaStream_t s2;
    cudaStreamCreate(&s2);
    cudaEvent_t e1, e2;
    cudaEventCreateWithFlags(&e1, cudaEventDisableTiming);
    cudaEventCreateWithFlags(&e2, cudaEventDisableTiming);

    cudaEventRecord(e1, 0);
    cudaStreamWaitEvent(s2, e1, 0);

    // side stream: CSR + dinv
    k_zero <<<nb_n, 256, 0, s2>>>(n);
    k_count<<<nb_e8, 256, 0, s2>>>(dst, ne);
    k_alloc<<<nb_n, 256, 0, s2>>>(n);
    k_fill <<<nb_e8, 256, 0, s2>>>(src, dst, ne);
    cudaEventRecord(e2, s2);

    // main stream: gemm1 concurrent with CSR build
    k_gemm<1><<<nb_g, 256>>>(x, W1, n);          // g_ht1 = fp16(x@W1), unscaled

    // join
    cudaStreamWaitEvent(0, e2, 0);

    k_gather<1><<<nb_w, 256>>>(nullptr, b1, n);  // g_agg1 = fp16(relu(.+b1))
    k_gemm<2><<<nb_g, 256>>>(nullptr, W2, n);    // g_ht2 = fp16((agg1@W2)*dinv)
    k_gather<2><<<nb_w, 256>>>(out, b2, n);      // out (fp32)

    cudaEventDestroy(e1);
    cudaEventDestroy(e2);
    cudaStreamDestroy(s2);
}